// round 12
// baseline (speedup 1.0000x reference)
#include <cuda_runtime.h>
#include <cuda_pipeline_primitives.h>
#include <cstdint>

// Spatial GCN (24x24 grid, adj = D^-1 A + I => 5-point stencil) + weight
// + BatchNorm2d(train) + LeakyReLU(0.2), fully fused, single plain launch.
//
// R12: persistent CTAs + double-buffered task pipeline. Grid = 2 CTAs/SM
// (all resident). Task = (channel, batch-quarter): 16 planes, 36.9KB. Each
// CTA loops over tasks (task = bid + round*grid) with two smem buffers:
// while task n computes from buffer (n&1), task n+2 streams into the other,
// and the buffer is refilled immediately after the stats pass (y is kept in
// registers, so no writeback and no apply-time smem reads). The DRAM read
// stream therefore continues through the reduce / rendezvous / store phases,
// breaking the chip-wide phase serialization seen in R2..R11.
// Per-channel stats: proven gmem rendezvous (publish -> atomic arrive ->
// acquire spin -> fixed-order combine -> last reader resets for replay).

#define GRID_N  24
#define NN      576
#define NQ      144              // float4 quads per plane
#define BATCH   64
#define CSPLIT  4                // tasks (CTAs' shares) per channel
#define PLANES  (BATCH / CSPLIT) // 16 planes per task
#define NTHR    576
#define BN_EPS  1e-4f
#define SLOPE   0.2f
#define MAXC    512

// rendezvous scratch (zero at load; self-reset to zero every launch)
__device__ float    g_part[MAXC * CSPLIT * 2];
__device__ unsigned g_cnt[MAXC];
__device__ unsigned g_done[MAXC];

__device__ __forceinline__ float invdeg(int i, int j) {
    const int d = 2 + (int)(i > 0 && i < GRID_N - 1) + (int)(j > 0 && j < GRID_N - 1);
    return (d == 2) ? 0.5f : ((d == 3) ? (1.f / 3.f) : 0.25f);
}

__global__ __launch_bounds__(NTHR, 2)
void gcn_bn_lrelu_kernel(const float* __restrict__ x,
                         const float* __restrict__ weight,
                         const float* __restrict__ gamma,
                         const float* __restrict__ beta,
                         float* __restrict__ out,
                         int C, int nTasks)
{
    extern __shared__ float buf[];             // 2 * PLANES * NN floats
    __shared__ float red[64];
    __shared__ float s_sb[2];

    const int bid  = blockIdx.x;
    const int gsz  = gridDim.x;
    const int t    = threadIdx.x;              // 0..575
    const int lane = t & 31;
    const int pq   = t / NQ;                   // 0..3
    const int q    = t - pq * NQ;              // quad 0..143
    const int row  = q / 6;
    const int col4 = q - row * 6;
    const int l0   = 4 * q;

    // ---- channel-invariant stencil coefficients (weight factored out) ----
    float idL[4], idR[4], idU[4], idD[4];
#pragma unroll
    for (int e = 0; e < 4; ++e) {
        const int j = 4 * col4 + e;
        idL[e] = (j > 0)           ? invdeg(row, j - 1) : 0.f;
        idR[e] = (j < GRID_N - 1)  ? invdeg(row, j + 1) : 0.f;
        idU[e] = (row > 0)         ? invdeg(row - 1, j) : 0.f;
        idD[e] = (row < GRID_N -1) ? invdeg(row + 1, j) : 0.f;
    }
    const int oL = (col4 > 0) ? l0 - 1 : l0;
    const int oR = (col4 < 5) ? l0 + 4 : l0;
    const int qU = (row > 0) ? q - 6 : q;
    const int qD = (row < GRID_N - 1) ? q + 6 : q;

    const float4* __restrict__ x4 = (const float4*)x;
    float4* __restrict__ out4 = (float4*)out;
    float4* buf4 = (float4*)buf;

    // prefetch task's 16 planes (4 per thread) into buffer sel; 1 commit
#define PREFETCH(TASK, SEL)                                                   \
    {                                                                         \
        if ((TASK) < nTasks) {                                                \
            const int pc = (TASK) >> 2, pr = (TASK) & 3;                      \
            _Pragma("unroll")                                                 \
            for (int h = 0; h < 4; ++h) {                                     \
                const int lp = pq + 4 * h;                                    \
                const int b  = pr * PLANES + lp;                              \
                __pipeline_memcpy_async(                                      \
                    &buf4[(size_t)((SEL) * PLANES + lp) * NQ + q],            \
                    x4 + ((size_t)(b * C + pc)) * NQ + q, 16);                \
            }                                                                 \
        }                                                                     \
        __pipeline_commit();                                                  \
    }

    // stencil for local plane LP of buffer SEL; w folded at the end
#define DO_STENCIL(SEL, LP, W, Y)                                             \
    {                                                                         \
        const float*  xb  = buf + (size_t)((SEL) * PLANES + (LP)) * NN;       \
        const float4* xb4 = (const float4*)xb;                                \
        const float4 ctr = xb4[q];                                            \
        const float4 up  = xb4[qU];                                           \
        const float4 dn  = xb4[qD];                                           \
        const float  lft = xb[oL];                                            \
        const float  rgt = xb[oR];                                            \
        float4 s;                                                             \
        s.x = ctr.x; s.x = fmaf(idL[0], lft,   s.x); s.x = fmaf(idR[0], ctr.y, s.x);  \
        s.x = fmaf(idU[0], up.x, s.x); s.x = fmaf(idD[0], dn.x, s.x);         \
        s.y = ctr.y; s.y = fmaf(idL[1], ctr.x, s.y); s.y = fmaf(idR[1], ctr.z, s.y);  \
        s.y = fmaf(idU[1], up.y, s.y); s.y = fmaf(idD[1], dn.y, s.y);         \
        s.z = ctr.z; s.z = fmaf(idL[2], ctr.y, s.z); s.z = fmaf(idR[2], ctr.w, s.z);  \
        s.z = fmaf(idU[2], up.z, s.z); s.z = fmaf(idD[2], dn.z, s.z);         \
        s.w = ctr.w; s.w = fmaf(idL[3], ctr.z, s.w); s.w = fmaf(idR[3], rgt,  s.w);   \
        s.w = fmaf(idU[3], up.w, s.w); s.w = fmaf(idD[3], dn.w, s.w);         \
        Y.x = (W).x * s.x; Y.y = (W).y * s.y;                                 \
        Y.z = (W).z * s.z; Y.w = (W).w * s.w;                                 \
    }

    // ---- prologue: prefetch first two tasks ----
    PREFETCH(bid, 0);
    PREFETCH(bid + gsz, 1);

    // ---- persistent task loop ----
    int sel = 0;
    for (int task = bid; task < nTasks; task += gsz, sel ^= 1) {
        const int c    = task >> 2;
        const int rank = task & 3;

        __pipeline_wait_prior(1);              // this task's group complete
        __syncthreads();

        const float4 w4 = ((const float4*)(weight + (size_t)c * NN))[q];

        // stats pass: 4 owned planes, y kept in registers (ILP = 4)
        float4 y0, y1, y2, y3;
        DO_STENCIL(sel, pq,      w4, y0);
        DO_STENCIL(sel, pq + 4,  w4, y1);
        DO_STENCIL(sel, pq + 8,  w4, y2);
        DO_STENCIL(sel, pq + 12, w4, y3);

        float sum = ((y0.x + y0.y) + (y0.z + y0.w)) + ((y1.x + y1.y) + (y1.z + y1.w))
                  + ((y2.x + y2.y) + (y2.z + y2.w)) + ((y3.x + y3.y) + (y3.z + y3.w));
        float sq = 0.f;
        sq = fmaf(y0.x, y0.x, sq); sq = fmaf(y0.y, y0.y, sq);
        sq = fmaf(y0.z, y0.z, sq); sq = fmaf(y0.w, y0.w, sq);
        sq = fmaf(y1.x, y1.x, sq); sq = fmaf(y1.y, y1.y, sq);
        sq = fmaf(y1.z, y1.z, sq); sq = fmaf(y1.w, y1.w, sq);
        sq = fmaf(y2.x, y2.x, sq); sq = fmaf(y2.y, y2.y, sq);
        sq = fmaf(y2.z, y2.z, sq); sq = fmaf(y2.w, y2.w, sq);
        sq = fmaf(y3.x, y3.x, sq); sq = fmaf(y3.y, y3.y, sq);
        sq = fmaf(y3.z, y3.z, sq); sq = fmaf(y3.w, y3.w, sq);

        __syncthreads();                       // all x reads of buffer done
        PREFETCH(task + 2 * gsz, sel);         // refill NOW (before the spin)

        // block reduction
#pragma unroll
        for (int off = 16; off > 0; off >>= 1) {
            sum += __shfl_down_sync(0xffffffffu, sum, off);
            sq  += __shfl_down_sync(0xffffffffu, sq,  off);
        }
        const int warp = t >> 5;               // 18 warps
        if (lane == 0) { red[warp] = sum; red[32 + warp] = sq; }
        __syncthreads();

        // gmem rendezvous across the channel's 4 tasks
        if (t == 0) {
            float s = 0.f, qq = 0.f;
#pragma unroll
            for (int wi = 0; wi < NTHR / 32; ++wi) { s += red[wi]; qq += red[32 + wi]; }
            float* slot = g_part + ((size_t)c * CSPLIT + rank) * 2;
            slot[0] = s; slot[1] = qq;
            __threadfence();
            atomicAdd(&g_cnt[c], 1u);

            unsigned v;
            do {
                asm volatile("ld.acquire.gpu.u32 %0, [%1];"
                             : "=r"(v) : "l"(&g_cnt[c]) : "memory");
            } while (v < CSPLIT);

            float st = 0.f, qt = 0.f;
            const float* base = g_part + (size_t)c * CSPLIT * 2;
#pragma unroll
            for (int r = 0; r < CSPLIT; ++r) { st += base[2 * r]; qt += base[2 * r + 1]; }

            const float inv_n = 1.f / (float)(BATCH * NN);
            float mean = st * inv_n;
            float var  = fmaf(qt, inv_n, -mean * mean);
            float rstd = rsqrtf(var + BN_EPS);
            float scv  = gamma[c] * rstd;
            s_sb[0] = scv;
            s_sb[1] = fmaf(-mean, scv, beta[c]);

            __threadfence();
            unsigned d = atomicAdd(&g_done[c], 1u);
            if (d == CSPLIT - 1) {   // last reader resets for the next replay
                asm volatile("st.relaxed.gpu.u32 [%0], %1;" :: "l"(&g_done[c]), "r"(0u) : "memory");
                asm volatile("st.relaxed.gpu.u32 [%0], %1;" :: "l"(&g_cnt[c]),  "r"(0u) : "memory");
            }
        }
        __syncthreads();
        const float sc = s_sb[0], bi = s_sb[1];

        // apply pass: registers -> normalize + LeakyReLU + STG.128
#define APPLY_STORE(Y, H)                                                     \
        {                                                                     \
            const int b = rank * PLANES + pq + 4 * (H);                       \
            float4 v;                                                         \
            v.x = fmaf(Y.x, sc, bi); v.y = fmaf(Y.y, sc, bi);                 \
            v.z = fmaf(Y.z, sc, bi); v.w = fmaf(Y.w, sc, bi);                 \
            v.x = (v.x >= 0.f) ? v.x : SLOPE * v.x;                           \
            v.y = (v.y >= 0.f) ? v.y : SLOPE * v.y;                           \
            v.z = (v.z >= 0.f) ? v.z : SLOPE * v.z;                           \
            v.w = (v.w >= 0.f) ? v.w : SLOPE * v.w;                           \
            out4[(size_t)(b * C + c) * NQ + q] = v;                           \
        }
        APPLY_STORE(y0, 0);
        APPLY_STORE(y1, 1);
        APPLY_STORE(y2, 2);
        APPLY_STORE(y3, 3);
#undef APPLY_STORE
    }
}

extern "C" void kernel_launch(void* const* d_in, const int* in_sizes, int n_in,
                              void* d_out, int out_size)
{
    const float* x      = (const float*)d_in[0];
    const float* weight = (const float*)d_in[2];
    const float* gamma  = (const float*)d_in[3];
    const float* beta   = (const float*)d_in[4];
    float* out = (float*)d_out;

    const int C = in_sizes[2] / NN;            // 512
    const int nTasks = C * CSPLIT;             // 2048

    int nsm = 148;
    cudaDeviceGetAttribute(&nsm, cudaDevAttrMultiProcessorCount, 0);
    const int grid = 2 * nsm;                  // all CTAs resident (2/SM)

    const size_t smem = (size_t)2 * PLANES * NN * sizeof(float);  // 73728 B
    cudaFuncSetAttribute(gcn_bn_lrelu_kernel,
                         cudaFuncAttributeMaxDynamicSharedMemorySize, (int)smem);
    gcn_bn_lrelu_kernel<<<grid, NTHR, smem>>>(x, weight, gamma, beta, out,
                                              C, nTasks);
}

// round 13
// speedup vs baseline: 1.0078x; 1.0078x over previous
#include <cuda_runtime.h>
#include <cuda_pipeline_primitives.h>
#include <cstdint>

// Spatial GCN (24x24 grid, adj = D^-1 A + I => 5-point stencil) + weight
// + BatchNorm2d(train) + LeakyReLU(0.2), fully fused, single plain launch.
//
// R13: R9 skeleton (288-thread CTAs, 4 per channel, x staged via cp.async,
// gmem rendezvous) with the y-storage machinery removed: the stats pass
// writes raw y straight to out (which stays L2-resident), and the apply
// pass re-reads it from L2 and normalizes in place. No y smem writeback,
// no y registers across barriers -> register cap 45 via launch_bounds
// (288, 5) -> 5 CTAs/SM (45 warps) instead of 4 (36 warps), attacking the
// register-file occupancy cap identified across R2-R12.

#define GRID_N  24
#define NN      576
#define NQ      144              // float4 quads per plane
#define BATCH   64
#define CSPLIT  4                // CTAs per channel
#define PLANES  (BATCH / CSPLIT) // 16 planes per CTA
#define PPC     4                // planes per chunk (2 per thread)
#define NCHUNK  (PLANES / PPC)   // 4
#define NTHR    288              // 2 plane-slots x 144 quads
#define BN_EPS  1e-4f
#define SLOPE   0.2f
#define MAXC    512

// rendezvous scratch (zero at load; self-reset to zero every launch)
__device__ float    g_part[MAXC * CSPLIT * 2];
__device__ unsigned g_cnt[MAXC];
__device__ unsigned g_done[MAXC];

__device__ __forceinline__ float invdeg(int i, int j) {
    const int d = 2 + (int)(i > 0 && i < GRID_N - 1) + (int)(j > 0 && j < GRID_N - 1);
    return (d == 2) ? 0.5f : ((d == 3) ? (1.f / 3.f) : 0.25f);
}

__global__ __launch_bounds__(NTHR, 5)
void gcn_bn_lrelu_kernel(const float* __restrict__ x,
                         const float* __restrict__ weight,
                         const float* __restrict__ gamma,
                         const float* __restrict__ beta,
                         float* __restrict__ out,
                         int C)
{
    __shared__ float buf[PLANES * NN];         // 36864 B (x only, read-only)
    __shared__ float red[24];
    __shared__ float s_sb[2];

    const int c    = blockIdx.x / CSPLIT;
    const int rank = blockIdx.x - c * CSPLIT;  // 0..3
    const int t    = threadIdx.x;              // 0..287
    const int lane = t & 31;
    const int ph   = t / NQ;                   // plane-slot 0..1
    const int q    = t - ph * NQ;              // quad 0..143
    const int row  = q / 6;
    const int col4 = q - row * 6;
    const int l0   = 4 * q;

    // ---- prologue: 4 cp.async groups, 2 planes per thread per group ----
    const float4* __restrict__ x4 = (const float4*)x;
    float4* buf4 = (float4*)buf;
#pragma unroll
    for (int s = 0; s < NCHUNK; ++s) {
#pragma unroll
        for (int h = 0; h < 2; ++h) {
            const int lp = s * PPC + ph + h * 2;           // local plane
            const int b  = rank * PLANES + lp;             // global plane
            __pipeline_memcpy_async(&buf4[(size_t)lp * NQ + q],
                                    x4 + ((size_t)(b * C + c)) * NQ + q, 16);
        }
        __pipeline_commit();
    }

    // ---- analytic coefficients folded with weight ----
    const float4 w4 = ((const float4*)(weight + (size_t)c * NN))[q];
    float cL[4], cR[4], cU[4], cD[4];
#pragma unroll
    for (int e = 0; e < 4; ++e) {
        const int j = 4 * col4 + e;
        const float we = (e == 0) ? w4.x : (e == 1) ? w4.y : (e == 2) ? w4.z : w4.w;
        cL[e] = (j > 0)           ? invdeg(row, j - 1) * we : 0.f;
        cR[e] = (j < GRID_N - 1)  ? invdeg(row, j + 1) * we : 0.f;
        cU[e] = (row > 0)         ? invdeg(row - 1, j) * we : 0.f;
        cD[e] = (row < GRID_N -1) ? invdeg(row + 1, j) * we : 0.f;
    }

    const int oL = (col4 > 0) ? l0 - 1 : l0;
    const int oR = (col4 < 5) ? l0 + 4 : l0;
    const int qU = (row > 0) ? q - 6 : q;
    const int qD = (row < GRID_N - 1) ? q + 6 : q;

    float4* __restrict__ out4 = (float4*)out;

#define DO_STENCIL(LP, Y)                                                     \
    {                                                                         \
        const float*  xb  = buf + (size_t)(LP) * NN;                          \
        const float4* xb4 = (const float4*)xb;                                \
        const float4 ctr = xb4[q];                                            \
        const float4 up  = xb4[qU];                                           \
        const float4 dn  = xb4[qD];                                           \
        const float  lft = xb[oL];                                            \
        const float  rgt = xb[oR];                                            \
        Y.x = w4.x*ctr.x; Y.x = fmaf(cL[0], lft,   Y.x); Y.x = fmaf(cR[0], ctr.y, Y.x); \
        Y.x = fmaf(cU[0], up.x, Y.x); Y.x = fmaf(cD[0], dn.x, Y.x);           \
        Y.y = w4.y*ctr.y; Y.y = fmaf(cL[1], ctr.x, Y.y); Y.y = fmaf(cR[1], ctr.z, Y.y); \
        Y.y = fmaf(cU[1], up.y, Y.y); Y.y = fmaf(cD[1], dn.y, Y.y);           \
        Y.z = w4.z*ctr.z; Y.z = fmaf(cL[2], ctr.y, Y.z); Y.z = fmaf(cR[2], ctr.w, Y.z); \
        Y.z = fmaf(cU[2], up.z, Y.z); Y.z = fmaf(cD[2], dn.z, Y.z);           \
        Y.w = w4.w*ctr.w; Y.w = fmaf(cL[3], ctr.z, Y.w); Y.w = fmaf(cR[3], rgt, Y.w);   \
        Y.w = fmaf(cU[3], up.w, Y.w); Y.w = fmaf(cD[3], dn.w, Y.w);           \
    }

    // ---- stats pass: stencil 2 planes/chunk, y straight to out, stats ----
    float sum = 0.f, sq = 0.f;
#pragma unroll
    for (int ch = 0; ch < NCHUNK; ++ch) {
        __pipeline_wait_prior(NCHUNK - 1 - ch);
        __syncthreads();                       // chunk ch resident
        const int lpA = ch * PPC + ph;
        const int lpB = lpA + 2;
        const int bA  = rank * PLANES + lpA;
        const int bB  = rank * PLANES + lpB;

        float4 yA, yB;
        DO_STENCIL(lpA, yA);
        DO_STENCIL(lpB, yB);

        sum += (yA.x + yA.y) + (yA.z + yA.w);
        sq = fmaf(yA.x, yA.x, sq); sq = fmaf(yA.y, yA.y, sq);
        sq = fmaf(yA.z, yA.z, sq); sq = fmaf(yA.w, yA.w, sq);
        sum += (yB.x + yB.y) + (yB.z + yB.w);
        sq = fmaf(yB.x, yB.x, sq); sq = fmaf(yB.y, yB.y, sq);
        sq = fmaf(yB.z, yB.z, sq); sq = fmaf(yB.w, yB.w, sq);

        out4[(size_t)(bA * C + c) * NQ + q] = yA;   // raw y -> L2
        out4[(size_t)(bB * C + c) * NQ + q] = yB;
        // buffer slots are never overwritten -> no trailing barrier
    }

    // ---- block reduction of this CTA's partial (sum, sq) ----
#pragma unroll
    for (int off = 16; off > 0; off >>= 1) {
        sum += __shfl_down_sync(0xffffffffu, sum, off);
        sq  += __shfl_down_sync(0xffffffffu, sq,  off);
    }
    const int warp = t >> 5;                   // 9 warps
    if (lane == 0) { red[warp] = sum; red[12 + warp] = sq; }
    __syncthreads();

    // ---- gmem rendezvous: publish partial, arrive, spin, combine ----
    if (t == 0) {
        float s = 0.f, qq = 0.f;
#pragma unroll
        for (int wi = 0; wi < NTHR / 32; ++wi) { s += red[wi]; qq += red[12 + wi]; }
        float* slot = g_part + ((size_t)c * CSPLIT + rank) * 2;
        slot[0] = s; slot[1] = qq;
        __threadfence();
        atomicAdd(&g_cnt[c], 1u);

        unsigned v;
        do {
            asm volatile("ld.acquire.gpu.u32 %0, [%1];"
                         : "=r"(v) : "l"(&g_cnt[c]) : "memory");
        } while (v < CSPLIT);

        float st = 0.f, qt = 0.f;
        const float* base = g_part + (size_t)c * CSPLIT * 2;
#pragma unroll
        for (int r = 0; r < CSPLIT; ++r) { st += base[2 * r]; qt += base[2 * r + 1]; }

        const float inv_n = 1.f / (float)(BATCH * NN);
        float mean = st * inv_n;
        float var  = fmaf(qt, inv_n, -mean * mean);
        float rstd = rsqrtf(var + BN_EPS);
        float sc   = gamma[c] * rstd;
        s_sb[0] = sc;
        s_sb[1] = fmaf(-mean, sc, beta[c]);

        __threadfence();
        unsigned d = atomicAdd(&g_done[c], 1u);
        if (d == CSPLIT - 1) {   // last reader resets for the next replay
            asm volatile("st.relaxed.gpu.u32 [%0], %1;" :: "l"(&g_done[c]), "r"(0u) : "memory");
            asm volatile("st.relaxed.gpu.u32 [%0], %1;" :: "l"(&g_cnt[c]),  "r"(0u) : "memory");
        }
    }
    __syncthreads();
    const float sc = s_sb[0], bi = s_sb[1];

    // ---- apply pass: re-read y from L2, normalize + LeakyReLU, in place ----
#pragma unroll
    for (int ch = 0; ch < NCHUNK; ++ch) {
        const int bA = rank * PLANES + ch * PPC + ph;
        const int bB = bA + 2;
        const size_t iA = (size_t)(bA * C + c) * NQ + q;
        const size_t iB = (size_t)(bB * C + c) * NQ + q;
        float4 vA = out4[iA];
        float4 vB = out4[iB];
        vA.x = fmaf(vA.x, sc, bi); vA.y = fmaf(vA.y, sc, bi);
        vA.z = fmaf(vA.z, sc, bi); vA.w = fmaf(vA.w, sc, bi);
        vB.x = fmaf(vB.x, sc, bi); vB.y = fmaf(vB.y, sc, bi);
        vB.z = fmaf(vB.z, sc, bi); vB.w = fmaf(vB.w, sc, bi);
        vA.x = (vA.x >= 0.f) ? vA.x : SLOPE * vA.x;
        vA.y = (vA.y >= 0.f) ? vA.y : SLOPE * vA.y;
        vA.z = (vA.z >= 0.f) ? vA.z : SLOPE * vA.z;
        vA.w = (vA.w >= 0.f) ? vA.w : SLOPE * vA.w;
        vB.x = (vB.x >= 0.f) ? vB.x : SLOPE * vB.x;
        vB.y = (vB.y >= 0.f) ? vB.y : SLOPE * vB.y;
        vB.z = (vB.z >= 0.f) ? vB.z : SLOPE * vB.z;
        vB.w = (vB.w >= 0.f) ? vB.w : SLOPE * vB.w;
        out4[iA] = vA;
        out4[iB] = vB;
    }
}

extern "C" void kernel_launch(void* const* d_in, const int* in_sizes, int n_in,
                              void* d_out, int out_size)
{
    const float* x      = (const float*)d_in[0];
    const float* weight = (const float*)d_in[2];
    const float* gamma  = (const float*)d_in[3];
    const float* beta   = (const float*)d_in[4];
    float* out = (float*)d_out;

    const int C = in_sizes[2] / NN;            // 512
    gcn_bn_lrelu_kernel<<<C * CSPLIT, NTHR>>>(x, weight, gamma, beta, out, C);
}